// round 1
// baseline (speedup 1.0000x reference)
#include <cuda_runtime.h>

// StochasticAttention collapses algebraically:
//   attention[b,q,v] = (sum_s softmax(...)[b,q,s]) * (sum_d V[b,v,d])
//                    = 1 * sum_d (x[b,v,:] @ w_value[d,:])
//                    = sum_f x[b,v,f] * (sum_d w_value[d,f])
// Output is independent of q (broadcast) and of all the PRNG/scatter/softmax work.

#define FDIM 1024
#define BDIM 16
#define DDIM 64

__device__ float g_wsum[FDIM];            // sum over d of w_value[d, f]
__device__ float g_rowsum[BDIM * FDIM];   // row[b,v] = x[b,v,:] . wsum

// Kernel 1: column-sum of w_value [D, F] -> wsum[F]. One block, 1024 threads.
__global__ void k_wsum(const float* __restrict__ w_value) {
    int f = threadIdx.x;
    float s = 0.f;
#pragma unroll
    for (int d = 0; d < DDIM; ++d)
        s += w_value[d * FDIM + f];
    g_wsum[f] = s;
}

// Kernel 2: row[b,v] = dot(x[b,v,:], wsum). One warp per row, 8 rows per block.
__global__ void k_rowsum(const float* __restrict__ x) {
    __shared__ float4 sw[FDIM / 4];
    int tid = threadIdx.x;
    const float4* w4 = reinterpret_cast<const float4*>(g_wsum);
    for (int i = tid; i < FDIM / 4; i += blockDim.x)
        sw[i] = w4[i];
    __syncthreads();

    int warp = tid >> 5;
    int lane = tid & 31;
    int row = blockIdx.x * 8 + warp;          // row in [0, B*F)
    const float4* xr = reinterpret_cast<const float4*>(x) + (size_t)row * (FDIM / 4);

    float acc = 0.f;
#pragma unroll
    for (int t = 0; t < 8; ++t) {
        int i = t * 32 + lane;                // coalesced float4 across the warp
        float4 a = xr[i];
        float4 b = sw[i];
        acc += a.x * b.x + a.y * b.y + a.z * b.z + a.w * b.w;
    }
#pragma unroll
    for (int off = 16; off; off >>= 1)
        acc += __shfl_xor_sync(0xffffffffu, acc, off);
    if (lane == 0)
        g_rowsum[row] = acc;
}

// Kernel 3: broadcast row[b,v] across q. out[b,q,v] = row[b,v].
// float4 indexing: per-b chunk = F*F/4 = 2^18 float4; per output row = 256 float4.
__global__ void k_bcast(float* __restrict__ out) {
    const float4* rs4 = reinterpret_cast<const float4*>(g_rowsum);
    float4* out4 = reinterpret_cast<float4*>(out);
    const unsigned stride = gridDim.x * blockDim.x;
    unsigned idx = blockIdx.x * blockDim.x + threadIdx.x;
    const unsigned total = (unsigned)BDIM * FDIM * FDIM / 4;  // 4,194,304
#pragma unroll 4
    for (; idx < total; idx += stride) {
        unsigned b  = idx >> 18;     // / (F*F/4)
        unsigned v4 = idx & 255u;    // float4 column within row
        out4[idx] = rs4[(b << 8) + v4];
    }
}

extern "C" void kernel_launch(void* const* d_in, const int* in_sizes, int n_in,
                              void* d_out, int out_size) {
    const float* x       = (const float*)d_in[0];  // [B,F,F]
    const float* w_value = (const float*)d_in[4];  // [D,F]
    float* out = (float*)d_out;                    // [B,F,F]
    (void)in_sizes; (void)n_in; (void)out_size;

    k_wsum<<<1, FDIM>>>(w_value);
    k_rowsum<<<(BDIM * FDIM) / 8, 256>>>(x);
    k_bcast<<<4096, 256>>>(out);
}

// round 2
// speedup vs baseline: 1.1275x; 1.1275x over previous
#include <cuda_runtime.h>

// StochasticAttention collapses algebraically:
//   attention[b,q,v] = (sum_s softmax(...)[b,q,s]) * (sum_d V[b,v,d])
//                    = 1 * sum_f x[b,v,f] * (sum_d w_value[d,f])
// Output is independent of q (broadcast). Single fused kernel:
//   grid = B * (F/VCHUNK) = 128 blocks, 1024 threads.
//   Phase 1: block-local wsum[f] = sum_d w_value[d,f] (w_value hits L2 after wave 1)
//   Phase 2: rowval[v] = dot(x[b,v,:], wsum) for the block's 128 v's (one warp/row)
//   Phase 3: broadcast rowvals across all q (coalesced 512B segments per warp)

#define FDIM 1024
#define BDIM 16
#define DDIM 64
#define VCHUNK 128

__global__ __launch_bounds__(1024, 1)
void k_fused(const float* __restrict__ x,
             const float* __restrict__ w_value,
             float* __restrict__ out) {
    __shared__ __align__(16) float4 s_part[4][FDIM / 4];  // 16 KB
    __shared__ __align__(16) float4 s_wsum[FDIM / 4];     // 4 KB
    __shared__ __align__(16) float  s_row[VCHUNK];        // 512 B

    const int tid   = threadIdx.x;
    const int b     = blockIdx.x >> 3;   // batch
    const int chunk = blockIdx.x & 7;    // v-chunk of 128
    const int warp  = tid >> 5;
    const int lane  = tid & 31;

    // ---- Phase 1: wsum = column-sum of w_value [D, F] ----
    {
        const int c   = tid & 255;       // float4 column (0..255)
        const int seg = tid >> 8;        // d-segment   (0..3), 16 d each
        const float4* w4 = reinterpret_cast<const float4*>(w_value);
        float4 acc = make_float4(0.f, 0.f, 0.f, 0.f);
#pragma unroll
        for (int d = 0; d < DDIM / 4; ++d) {
            float4 v = w4[(size_t)(seg * (DDIM / 4) + d) * (FDIM / 4) + c];
            acc.x += v.x; acc.y += v.y; acc.z += v.z; acc.w += v.w;
        }
        s_part[seg][c] = acc;
    }
    __syncthreads();
    if (tid < FDIM / 4) {
        float4 a = s_part[0][tid], p1 = s_part[1][tid];
        float4 p2 = s_part[2][tid], p3 = s_part[3][tid];
        float4 r;
        r.x = a.x + p1.x + p2.x + p3.x;
        r.y = a.y + p1.y + p2.y + p3.y;
        r.z = a.z + p1.z + p2.z + p3.z;
        r.w = a.w + p1.w + p2.w + p3.w;
        s_wsum[tid] = r;
    }
    __syncthreads();

    // ---- Phase 2: 128 dot products, one warp per row, 4 rows per warp ----
    const float4* x4 = reinterpret_cast<const float4*>(x);
    const size_t xbase = ((size_t)b * FDIM + (size_t)chunk * VCHUNK) * (FDIM / 4);
#pragma unroll
    for (int r = 0; r < 4; ++r) {
        const int row = warp * 4 + r;
        const float4* xr = x4 + xbase + (size_t)row * (FDIM / 4);
        float acc = 0.f;
#pragma unroll
        for (int t = 0; t < 8; ++t) {
            float4 a = xr[t * 32 + lane];
            float4 w = s_wsum[t * 32 + lane];
            acc += a.x * w.x + a.y * w.y + a.z * w.z + a.w * w.w;
        }
#pragma unroll
        for (int off = 16; off; off >>= 1)
            acc += __shfl_xor_sync(0xffffffffu, acc, off);
        if (lane == 0) s_row[row] = acc;
    }
    __syncthreads();

    // ---- Phase 3: broadcast across q. Warp w handles q = w, w+32, ... ----
    // Each lane writes one float4 (lanes 0..31 cover the 128-float chunk);
    // a warp's 32 lanes write 512B contiguous per q-row.
    const float4 myval = reinterpret_cast<const float4*>(s_row)[lane];
    float4* out4 = reinterpret_cast<float4*>(out);
    const size_t obase = (size_t)b * FDIM * (FDIM / 4) + (size_t)chunk * (VCHUNK / 4);
#pragma unroll 8
    for (int q = warp; q < FDIM; q += 32) {
        out4[obase + (size_t)q * (FDIM / 4) + lane] = myval;
    }
}

extern "C" void kernel_launch(void* const* d_in, const int* in_sizes, int n_in,
                              void* d_out, int out_size) {
    const float* x       = (const float*)d_in[0];  // [B,F,F]
    const float* w_value = (const float*)d_in[4];  // [D,F]
    float* out = (float*)d_out;                    // [B,F,F]
    (void)in_sizes; (void)n_in; (void)out_size;

    k_fused<<<BDIM * (FDIM / VCHUNK), 1024>>>(x, w_value, out);
}

// round 4
// speedup vs baseline: 1.2062x; 1.0698x over previous
#include <cuda_runtime.h>

// StochasticAttention collapses algebraically:
//   attention[b,q,v] = (sum_s softmax(...)[b,q,s]) * (sum_d V[b,v,d])
//                    = sum_f x[b,v,f] * (sum_d w_value[d,f])
// Output independent of q (row broadcast).
//
// Single fused kernel, grid = 128 blocks x 1024 threads, block = (b, 128-v chunk).
// Pipelined in 4 sub-chunks of 32 rows so x-reads and out-writes overlap
// (full-duplex HBM): compute 32 dots -> sync -> issue stores + next loads.

#define FDIM 1024
#define BDIM 16
#define DDIM 64

__global__ __launch_bounds__(1024, 1)
void k_fused(const float* __restrict__ x,
             const float* __restrict__ w_value,
             float* __restrict__ out) {
    __shared__ __align__(16) float4 s_part[4][FDIM / 4];  // 16 KB
    __shared__ __align__(16) float4 s_wsum[FDIM / 4];     // 4 KB
    __shared__ __align__(16) float  s_row[4][32];         // 512 B, one buffer per sub-chunk

    const int tid  = threadIdx.x;
    const int warp = tid >> 5;
    const int lane = tid & 31;
    const int b     = blockIdx.x >> 3;
    const int chunk = blockIdx.x & 7;

    const float4* x4 = reinterpret_cast<const float4*>(x);
    const unsigned rowbase = ((unsigned)b << 10) + ((unsigned)chunk << 7);

    // ---- Prefetch sub-chunk 0 (issued before phase 1 to hide wsum latency) ----
    float4 a[8];
    {
        const float4* xr = x4 + (size_t)(rowbase + warp) * (FDIM / 4);
#pragma unroll
        for (int t = 0; t < 8; ++t) a[t] = xr[t * 32 + lane];
    }

    // ---- Phase 1: wsum = column-sum of w_value [D, F] (L2-deduped across blocks) ----
    {
        const int c   = tid & 255;
        const int seg = tid >> 8;
        const float4* w4 = reinterpret_cast<const float4*>(w_value);
        float4 acc = make_float4(0.f, 0.f, 0.f, 0.f);
#pragma unroll
        for (int d = 0; d < DDIM / 4; ++d) {
            float4 v = w4[(size_t)(seg * (DDIM / 4) + d) * (FDIM / 4) + c];
            acc.x += v.x; acc.y += v.y; acc.z += v.z; acc.w += v.w;
        }
        s_part[seg][c] = acc;
    }
    __syncthreads();
    if (tid < FDIM / 4) {
        float4 p0 = s_part[0][tid], p1 = s_part[1][tid];
        float4 p2 = s_part[2][tid], p3 = s_part[3][tid];
        float4 r;
        r.x = p0.x + p1.x + p2.x + p3.x;
        r.y = p0.y + p1.y + p2.y + p3.y;
        r.z = p0.z + p1.z + p2.z + p3.z;
        r.w = p0.w + p1.w + p2.w + p3.w;
        s_wsum[tid] = r;
    }
    __syncthreads();

    // ---- Pipelined sub-chunks: 32 rows each; warp w owns row (s*32 + w) ----
    float4* out4 = reinterpret_cast<float4*>(out);
    const int qsub = lane >> 3;          // which of 4 q-rows this lane writes
    const int col  = lane & 7;           // which float4 within the 32-v segment
    const unsigned obase = ((unsigned)b << 18) + ((unsigned)chunk << 5);  // float4 units

#pragma unroll
    for (int s = 0; s < 4; ++s) {
        // dot product of preloaded row with wsum
        float acc = 0.f;
#pragma unroll
        for (int t = 0; t < 8; ++t) {
            float4 w = s_wsum[t * 32 + lane];
            acc += a[t].x * w.x + a[t].y * w.y + a[t].z * w.z + a[t].w * w.w;
        }
        // issue next sub-chunk's loads early (overlap DRAM latency with reduce+stores)
        if (s < 3) {
            const float4* xr = x4 + (size_t)(rowbase + (s + 1) * 32 + warp) * (FDIM / 4);
#pragma unroll
            for (int t = 0; t < 8; ++t) a[t] = xr[t * 32 + lane];
        }
#pragma unroll
        for (int off = 16; off; off >>= 1)
            acc += __shfl_xor_sync(0xffffffffu, acc, off);
        if (lane == 0) s_row[s][warp] = acc;
        __syncthreads();

        // broadcast-write these 32 v's across all 1024 q.
        // Per q-row, 8 lanes (fixed qsub) write 8 consecutive float4 = 128B.
        const float4 val = reinterpret_cast<const float4*>(s_row[s])[col];
        const unsigned vbase = obase + ((unsigned)s << 3);
#pragma unroll
        for (int it = 0; it < 8; ++it) {
            unsigned q = (unsigned)it * 128u + (unsigned)warp * 4u + (unsigned)qsub;
            out4[vbase + q * (FDIM / 4) + (unsigned)col] = val;
        }
    }
}

extern "C" void kernel_launch(void* const* d_in, const int* in_sizes, int n_in,
                              void* d_out, int out_size) {
    const float* x       = (const float*)d_in[0];  // [B,F,F]
    const float* w_value = (const float*)d_in[4];  // [D,F]
    float* out = (float*)d_out;                    // [B,F,F]
    (void)in_sizes; (void)n_in; (void)out_size;

    k_fused<<<BDIM * (FDIM / 128), 1024>>>(x, w_value, out);
}